// round 10
// baseline (speedup 1.0000x reference)
#include <cuda_runtime.h>
#include <cuda_bf16.h>

#define BATCH 8192
#define TMAX  2048
#define ROWSTRIDE (TMAX + 1)   // 2049 ints per row (last element is T)
#define TILE 256               // 8 elements per lane, warp handles 2 rows

// Layered LUT: layer v (v=0..8) = products of v consecutive per-obs matrices,
// layer base = 2^v - 1, entry index = obs bits (chronologically first = LSB).
// 511 entries. float4 = (c00, c01, c10, c11); alpha' = C * alpha.

// Ordered reduce of lane-chunk matrices into lane 0 (lane 0 earliest in time),
// fold into running product r (lane 0 authoritative), broadcast fold-sum.
__device__ __forceinline__ float reduce_fold(float c00, float c01, float c10, float c11,
                                             float& r00, float& r01, float& r10, float& r11,
                                             int lane) {
    #pragma unroll
    for (int d = 1; d < 32; d <<= 1) {
        const float u00 = __shfl_down_sync(0xFFFFFFFFu, c00, d);
        const float u01 = __shfl_down_sync(0xFFFFFFFFu, c01, d);
        const float u10 = __shfl_down_sync(0xFFFFFFFFu, c10, d);
        const float u11 = __shfl_down_sync(0xFFFFFFFFu, c11, d);
        if (lane + d < 32) {                    // u is LATER in time: c = u * c
            const float q00 = u00 * c00 + u01 * c10;
            const float q01 = u00 * c01 + u01 * c11;
            const float q10 = u10 * c00 + u11 * c10;
            const float q11 = u10 * c01 + u11 * c11;
            c00 = q00; c01 = q01; c10 = q10; c11 = q11;
        }
    }
    if (lane == 0) {
        const float q00 = c00 * r00 + c01 * r10;
        const float q01 = c00 * r01 + c01 * r11;
        const float q10 = c10 * r00 + c11 * r10;
        const float q11 = c10 * r01 + c11 * r11;
        r00 = q00; r01 = q01; r10 = q10; r11 = q11;
    }
    // nonneg entries: sum == 0 <=> product exactly zero (and stays zero)
    const float s = r00 + r01 + r10 + r11;
    return __shfl_sync(0xFFFFFFFFu, s, 0);
}

struct RowCtx {
    int T, x0, t0, pos0;
    int pk1, pk2, pk3;
    int4 fa, fb;
};

__device__ __forceinline__ void issue_row_loads(const int* __restrict__ row,
                                                int row_id, int lane, RowCtx& c) {
    c.T  = row[TMAX];
    c.x0 = row[0];
    const int mis = (row_id + 1) & 3;          // row base ≡ (row_id+1) mod 4 ints
    c.t0 = 1 + ((4 - mis) & 3);                // 16B-aligned start, in [1,4]
    c.pk1 = (c.t0 > 1) ? row[1] : 0;
    c.pk2 = (c.t0 > 2) ? row[2] : 0;
    c.pk3 = (c.t0 > 3) ? row[3] : 0;
    c.pos0 = c.t0 + (lane << 3);               // <= 252: always in-bounds
    const int4* p = (const int4*)(row + c.pos0);
    c.fa = p[0];
    c.fb = p[1];
}

__device__ __forceinline__ void process_row(const int* __restrict__ row,
                                            const RowCtx& c, int lane,
                                            const float4* __restrict__ slut,
                                            const float2* __restrict__ a0tab,
                                            float* __restrict__ outp) {
    // peel elements [1, min(t0,T)) via LUT layer 1
    float r00 = 1.f, r01 = 0.f, r10 = 0.f, r11 = 1.f;
    const int pe = c.t0 < c.T ? c.t0 : c.T;
    if (pe > 1) { const float4 M = slut[1 + c.pk1]; r00 = M.x; r01 = M.y; r10 = M.z; r11 = M.w; }
    if (pe > 2) {
        const float4 M = slut[1 + c.pk2];
        const float q00 = M.x * r00 + M.y * r10, q01 = M.x * r01 + M.y * r11;
        const float q10 = M.z * r00 + M.w * r10, q11 = M.z * r01 + M.w * r11;
        r00 = q00; r01 = q01; r10 = q10; r11 = q11;
    }
    if (pe > 3) {
        const float4 M = slut[1 + c.pk3];
        const float q00 = M.x * r00 + M.y * r10, q01 = M.x * r01 + M.y * r11;
        const float q10 = M.z * r00 + M.w * r10, q11 = M.z * r01 + M.w * r11;
        r00 = q00; r01 = q01; r10 = q10; r11 = q11;
    }

    if (c.t0 < c.T) {
        // first tile: single-lookup 8-bit layered LUT
        const int idx8 = c.fa.x | (c.fa.y << 1) | (c.fa.z << 2) | (c.fa.w << 3)
                       | (c.fb.x << 4) | (c.fb.y << 5) | (c.fb.z << 6) | (c.fb.w << 7);
        int rem = c.T - c.pos0;
        rem = rem < 0 ? 0 : (rem > 8 ? 8 : rem);
        const int mask = (1 << rem) - 1;
        const float4 M = slut[mask + (idx8 & mask)];
        float sum = reduce_fold(M.x, M.y, M.z, M.w, r00, r01, r10, r11, lane);

        // later tiles: rare (only if no underflow yet)
        #pragma unroll 1
        for (int s = c.t0 + TILE; s < c.T && sum != 0.0f; s += TILE) {
            const int pos = s + (lane << 3);
            int4 a = make_int4(0, 0, 0, 0), b = a;
            if (pos < c.T) {
                if (pos + 8 <= ROWSTRIDE) {
                    const int4* p = (const int4*)(row + pos);
                    a = p[0]; b = p[1];
                } else {                       // tail at the very row end
                    const int v = c.T - pos;   // <= 6 here
                    a.x = row[pos];
                    if (v > 1) a.y = row[pos + 1];
                    if (v > 2) a.z = row[pos + 2];
                    if (v > 3) a.w = row[pos + 3];
                    if (v > 4) b.x = row[pos + 4];
                    if (v > 5) b.y = row[pos + 5];
                }
            }
            const int idx2 = a.x | (a.y << 1) | (a.z << 2) | (a.w << 3)
                           | (b.x << 4) | (b.y << 5) | (b.z << 6) | (b.w << 7);
            int rem2 = c.T - pos;
            rem2 = rem2 < 0 ? 0 : (rem2 > 8 ? 8 : rem2);
            const int mask2 = (1 << rem2) - 1;
            const float4 M2 = slut[mask2 + (idx2 & mask2)];
            sum = reduce_fold(M2.x, M2.y, M2.z, M2.w, r00, r01, r10, r11, lane);
        }
    }

    if (lane == 0) {
        const float2 al = a0tab[c.x0];
        *outp = (r00 * al.x + r01 * al.y) + (r10 * al.x + r11 * al.y);
    }
}

__global__ __launch_bounds__(256)
void hmm_fwd_kernel(const int* __restrict__ xin,
                    const float* __restrict__ prior_l,
                    const float* __restrict__ trans_l,
                    const float* __restrict__ emis_l,
                    float* __restrict__ out) {
    __shared__ float4 slut[511];
    __shared__ float2 a0tab[2];

    const int tid  = threadIdx.x;
    const int wid  = tid >> 5;
    const int lane = tid & 31;

    const int row0 = (blockIdx.x * 8 + wid) * 2;   // warp owns rows row0, row0+1
    const int* __restrict__ rp0 = xin + (size_t)row0 * ROWSTRIDE;
    const int* __restrict__ rp1 = rp0 + ROWSTRIDE;

    // ---- issue ALL loads for both rows before anything else (max MLP) ----
    RowCtx c0, c1;
    issue_row_loads(rp0, row0,     lane, c0);
    issue_row_loads(rp1, row0 + 1, lane, c1);

    // ---- constants (all threads, trivial) + LUT build (2 entries/thread) ----
    {
        float pe0 = __expf(prior_l[0]), pe1 = __expf(prior_l[1]);
        float pinv = 1.0f / (pe0 + pe1);
        const float p0f = pe0 * pinv, p1f = pe1 * pinv;

        float t00 = __expf(trans_l[0]), t01 = __expf(trans_l[1]);
        float t10 = __expf(trans_l[2]), t11 = __expf(trans_l[3]);
        float rr0 = 1.0f / (t00 + t01), rr1 = 1.0f / (t10 + t11);
        const float A00 = t00 * rr0, A01 = t01 * rr0;
        const float A10 = t10 * rr1, A11 = t11 * rr1;

        float e00x = __expf(emis_l[0]), e01x = __expf(emis_l[1]);
        float e10x = __expf(emis_l[2]), e11x = __expf(emis_l[3]);
        float s0 = 1.0f / (e00x + e01x), s1 = 1.0f / (e10x + e11x);
        const float E00 = e00x * s0, E01 = e01x * s0;
        const float E10 = e10x * s1, E11 = e11x * s1;

        const float Ma00 = E00 * A00, Ma01 = E00 * A10, Ma10 = E10 * A01, Ma11 = E10 * A11;
        const float Mb00 = E01 * A00, Mb01 = E01 * A10, Mb10 = E11 * A01, Mb11 = E11 * A11;

        if (tid == 255) {
            a0tab[0] = make_float2(E00 * p0f, E10 * p1f);
            a0tab[1] = make_float2(E01 * p0f, E11 * p1f);
        }
        // thread tid builds entries tid and tid+256 (tid<255)
        #pragma unroll
        for (int e = tid; e < 511; e += 256) {
            const int n = e + 1;
            const int v = 31 - __clz(n);       // layer
            const int idx = n - (1 << v);      // obs bits
            float c00 = 1.f, c01 = 0.f, c10 = 0.f, c11 = 1.f;
            for (int i = 0; i < v; ++i) {
                const int b = (idx >> i) & 1;
                const float m00 = b ? Mb00 : Ma00, m01 = b ? Mb01 : Ma01;
                const float m10 = b ? Mb10 : Ma10, m11 = b ? Mb11 : Ma11;
                const float q00 = m00 * c00 + m01 * c10;
                const float q01 = m00 * c01 + m01 * c11;
                const float q10 = m10 * c00 + m11 * c10;
                const float q11 = m10 * c01 + m11 * c11;
                c00 = q00; c01 = q01; c10 = q10; c11 = q11;
            }
            slut[e] = make_float4(c00, c01, c10, c11);
        }
    }
    __syncthreads();

    process_row(rp0, c0, lane, slut, a0tab, out + row0);
    process_row(rp1, c1, lane, slut, a0tab, out + row0 + 1);
}

extern "C" void kernel_launch(void* const* d_in, const int* in_sizes, int n_in,
                              void* d_out, int out_size) {
    const int*   xin     = (const int*)d_in[0];
    const float* prior_l = (const float*)d_in[1];
    const float* trans_l = (const float*)d_in[2];
    const float* emis_l  = (const float*)d_in[3];
    float* out = (float*)d_out;

    const int blocks = BATCH / 16;     // 512 blocks, 8 warps, 2 rows per warp
    hmm_fwd_kernel<<<blocks, 256>>>(xin, prior_l, trans_l, emis_l, out);
}

// round 12
// speedup vs baseline: 1.1066x; 1.1066x over previous
#include <cuda_runtime.h>
#include <cuda_bf16.h>

#define BATCH 8192
#define TMAX  2048
#define ROWSTRIDE (TMAX + 1)   // 2049 ints per row (last element is T)
#define TILE 256               // 8 elements per lane, warp-per-row

// Register-resident layered LUT, one entry per lane:
//   lane k holds entry k; entry 0 = identity; layer v (v=1..4) at base 2^v-1,
//   entry e is a product of v consecutive per-obs matrices where
//   v = floor(log2(e+1)), obs bits = (e+1) - 2^v (chronologically first = LSB).
//   Entries 0..30 used; lane 31 holds identity (never looked up).
// float4 = (c00, c01, c10, c11); alpha' = C * alpha.

__device__ __forceinline__ float4 lut_get(const float4 mine, int e) {
    float4 r;
    r.x = __shfl_sync(0xFFFFFFFFu, mine.x, e);
    r.y = __shfl_sync(0xFFFFFFFFu, mine.y, e);
    r.z = __shfl_sync(0xFFFFFFFFu, mine.z, e);
    r.w = __shfl_sync(0xFFFFFFFFu, mine.w, e);
    return r;
}

// Ordered reduce (lane 0 earliest) into lane 0, fold into r, broadcast sum.
__device__ __forceinline__ float reduce_fold(float c00, float c01, float c10, float c11,
                                             float& r00, float& r01, float& r10, float& r11,
                                             int lane) {
    #pragma unroll
    for (int d = 1; d < 32; d <<= 1) {
        const float u00 = __shfl_down_sync(0xFFFFFFFFu, c00, d);
        const float u01 = __shfl_down_sync(0xFFFFFFFFu, c01, d);
        const float u10 = __shfl_down_sync(0xFFFFFFFFu, c10, d);
        const float u11 = __shfl_down_sync(0xFFFFFFFFu, c11, d);
        if (lane + d < 32) {                    // u is LATER in time: c = u * c
            const float q00 = u00 * c00 + u01 * c10;
            const float q01 = u00 * c01 + u01 * c11;
            const float q10 = u10 * c00 + u11 * c10;
            const float q11 = u10 * c01 + u11 * c11;
            c00 = q00; c01 = q01; c10 = q10; c11 = q11;
        }
    }
    if (lane == 0) {
        const float q00 = c00 * r00 + c01 * r10;
        const float q01 = c00 * r01 + c01 * r11;
        const float q10 = c10 * r00 + c11 * r10;
        const float q11 = c10 * r01 + c11 * r11;
        r00 = q00; r01 = q01; r10 = q10; r11 = q11;
    }
    // nonneg entries: sum == 0 <=> product exactly zero (and stays zero)
    const float s = r00 + r01 + r10 + r11;
    return __shfl_sync(0xFFFFFFFFu, s, 0);
}

__global__ __launch_bounds__(256)
void hmm_fwd_kernel(const int* __restrict__ xin,
                    const float* __restrict__ prior_l,
                    const float* __restrict__ trans_l,
                    const float* __restrict__ emis_l,
                    float* __restrict__ out) {
    const int tid  = threadIdx.x;
    const int wid  = tid >> 5;
    const int lane = tid & 31;
    const int row_id = blockIdx.x * 8 + wid;   // warp-per-row, fully independent

    const int* __restrict__ row = xin + (size_t)row_id * ROWSTRIDE;

    // ---- issue all loads first; their latency hides the constant build ----
    const int T  = row[TMAX];
    const int x0 = row[0];
    const int mis = (row_id + 1) & 3;          // row base ≡ (row_id+1) mod 4 ints
    const int t0  = 1 + ((4 - mis) & 3);       // 16B-aligned start, in [1,4]
    const int pk1 = (t0 > 1) ? row[1] : 0;
    const int pk2 = (t0 > 2) ? row[2] : 0;
    const int pk3 = (t0 > 3) ? row[3] : 0;

    const int pos0 = t0 + (lane << 3);         // <= 252: always in-bounds
    const int4* p0 = (const int4*)(row + pos0);
    const int4 fa = p0[0];
    const int4 fb = p0[1];

    // ---- softmax constants (all lanes, SIMT) ----
    float pe0 = __expf(prior_l[0]), pe1 = __expf(prior_l[1]);
    float pinv = 1.0f / (pe0 + pe1);
    const float p0f = pe0 * pinv, p1f = pe1 * pinv;

    float t00 = __expf(trans_l[0]), t01 = __expf(trans_l[1]);
    float t10 = __expf(trans_l[2]), t11 = __expf(trans_l[3]);
    float rr0 = 1.0f / (t00 + t01), rr1 = 1.0f / (t10 + t11);
    const float A00 = t00 * rr0, A01 = t01 * rr0;
    const float A10 = t10 * rr1, A11 = t11 * rr1;

    float e00x = __expf(emis_l[0]), e01x = __expf(emis_l[1]);
    float e10x = __expf(emis_l[2]), e11x = __expf(emis_l[3]);
    float s0 = 1.0f / (e00x + e01x), s1 = 1.0f / (e10x + e11x);
    const float E00 = e00x * s0, E01 = e01x * s0;
    const float E10 = e10x * s1, E11 = e11x * s1;

    const float Ma00 = E00 * A00, Ma01 = E00 * A10, Ma10 = E10 * A01, Ma11 = E10 * A11;
    const float Mb00 = E01 * A00, Mb01 = E01 * A10, Mb10 = E11 * A01, Mb11 = E11 * A11;

    // ---- each lane builds LUT entry 'lane' in registers ----
    // entry e: n = e+1, layer v = floor(log2(n)), obs bits idx = n - 2^v
    float4 mine = make_float4(1.f, 0.f, 0.f, 1.f);   // lane 0 (identity), lane 31 unused
    if (lane >= 1 && lane <= 30) {
        const int n = lane + 1;
        const int v = 31 - __clz(n);           // layer
        const int idx = n - (1 << v);          // obs bits
        float c00 = 1.f, c01 = 0.f, c10 = 0.f, c11 = 1.f;
        for (int i = 0; i < v; ++i) {
            const int b = (idx >> i) & 1;
            const float m00 = b ? Mb00 : Ma00, m01 = b ? Mb01 : Ma01;
            const float m10 = b ? Mb10 : Ma10, m11 = b ? Mb11 : Ma11;
            const float q00 = m00 * c00 + m01 * c10;
            const float q01 = m00 * c01 + m01 * c11;
            const float q10 = m10 * c00 + m11 * c10;
            const float q11 = m10 * c01 + m11 * c11;
            c00 = q00; c01 = q01; c10 = q10; c11 = q11;
        }
        mine = make_float4(c00, c01, c10, c11);
    }

    // ---- peel elements [1, min(t0,T)) with a single layered lookup ----
    const int pe = t0 < T ? t0 : T;            // peel length = pe-1, in [0,3]
    const int pidx  = pk1 + 2 * pk2 + 4 * pk3;
    const int pmask = (1 << (pe - 1)) - 1;
    const float4 P = lut_get(mine, pmask + (pidx & pmask));
    float r00 = P.x, r01 = P.y, r10 = P.z, r11 = P.w;

    if (t0 < T) {
        // ---- first tile (data already in flight) ----
        const int idxA = fa.x + 2 * fa.y + 4 * fa.z + 8 * fa.w;
        const int idxB = fb.x + 2 * fb.y + 4 * fb.z + 8 * fb.w;
        int rem = T - pos0;
        rem = rem < 0 ? 0 : (rem > 8 ? 8 : rem);
        const int vA = rem < 4 ? rem : 4;
        const int vB = rem - vA;
        const int mA = (1 << vA) - 1, mB = (1 << vB) - 1;
        const float4 MA = lut_get(mine, mA + (idxA & mA));
        const float4 MB = lut_get(mine, mB + (idxB & mB));

        const float c00 = MB.x * MA.x + MB.y * MA.z;
        const float c01 = MB.x * MA.y + MB.y * MA.w;
        const float c10 = MB.z * MA.x + MB.w * MA.z;
        const float c11 = MB.z * MA.y + MB.w * MA.w;
        float sum = reduce_fold(c00, c01, c10, c11, r00, r01, r10, r11, lane);

        // ---- later tiles: essentially never run (underflow break) ----
        #pragma unroll 1
        for (int s = t0 + TILE; s < T && sum != 0.0f; s += TILE) {
            const int pos = s + (lane << 3);
            int4 a = make_int4(0, 0, 0, 0), b = a;
            if (pos < T) {
                if (pos + 8 <= ROWSTRIDE) {
                    const int4* p = (const int4*)(row + pos);
                    a = p[0]; b = p[1];
                } else {                       // tail at the very row end
                    const int v = T - pos;     // <= 6 here
                    a.x = row[pos];
                    if (v > 1) a.y = row[pos + 1];
                    if (v > 2) a.z = row[pos + 2];
                    if (v > 3) a.w = row[pos + 3];
                    if (v > 4) b.x = row[pos + 4];
                    if (v > 5) b.y = row[pos + 5];
                }
            }
            const int iA = a.x + 2 * a.y + 4 * a.z + 8 * a.w;
            const int iB = b.x + 2 * b.y + 4 * b.z + 8 * b.w;
            int rem2 = T - pos;
            rem2 = rem2 < 0 ? 0 : (rem2 > 8 ? 8 : rem2);
            const int vA2 = rem2 < 4 ? rem2 : 4;
            const int vB2 = rem2 - vA2;
            const int mA2 = (1 << vA2) - 1, mB2 = (1 << vB2) - 1;
            const float4 MA2 = lut_get(mine, mA2 + (iA & mA2));
            const float4 MB2 = lut_get(mine, mB2 + (iB & mB2));
            const float d00 = MB2.x * MA2.x + MB2.y * MA2.z;
            const float d01 = MB2.x * MA2.y + MB2.y * MA2.w;
            const float d10 = MB2.z * MA2.x + MB2.w * MA2.z;
            const float d11 = MB2.z * MA2.y + MB2.w * MA2.w;
            sum = reduce_fold(d00, d01, d10, d11, r00, r01, r10, r11, lane);
        }
    }

    if (lane == 0) {
        const float al0 = (x0 ? E01 : E00) * p0f;
        const float al1 = (x0 ? E11 : E10) * p1f;
        out[row_id] = (r00 * al0 + r01 * al1) + (r10 * al0 + r11 * al1);
    }
}

extern "C" void kernel_launch(void* const* d_in, const int* in_sizes, int n_in,
                              void* d_out, int out_size) {
    const int*   xin     = (const int*)d_in[0];
    const float* prior_l = (const float*)d_in[1];
    const float* trans_l = (const float*)d_in[2];
    const float* emis_l  = (const float*)d_in[3];
    float* out = (float*)d_out;

    const int blocks = BATCH / 8;      // 1024 blocks, 8 independent warps each
    hmm_fwd_kernel<<<blocks, 256>>>(xin, prior_l, trans_l, emis_l, out);
}